// round 1
// baseline (speedup 1.0000x reference)
#include <cuda_runtime.h>
#include <cuda_bf16.h>

#define BATCH 4
#define SEQ   2048
#define EMB   1024
#define HS    64

// Scratch for Q, K, V projections ([B*T, HS] each). __device__ globals per
// allocation rules.
__device__ float g_Q[BATCH * SEQ * HS];
__device__ float g_K[BATCH * SEQ * HS];
__device__ float g_V[BATCH * SEQ * HS];

// ---------------------------------------------------------------------------
// Kernel A: projection GEMM.  out[m][n] = sum_c x[m][c] * W[n][c]
// M = B*T = 8192, K = 1024, N = 64.  blockIdx.y in {0,1,2} selects Wq/Wk/Wv.
// 64x64 output tile per CTA, 256 threads, 4x4 register blocking.
// ---------------------------------------------------------------------------
__global__ __launch_bounds__(256) void proj_kernel(
    const float* __restrict__ x,
    const float* __restrict__ Wq,
    const float* __restrict__ Wk,
    const float* __restrict__ Wv)
{
    __shared__ float Xs[64][65];   // +1 pad: avoid stride-64 bank conflicts
    __shared__ float Ws[64][65];

    const int mblk  = blockIdx.x;      // 0..127
    const int which = blockIdx.y;      // 0..2
    const float* W  = (which == 0) ? Wq : ((which == 1) ? Wk : Wv);
    float* out      = (which == 0) ? g_Q : ((which == 1) ? g_K : g_V);

    const int tid = threadIdx.x;
    const int ty  = tid >> 4;          // 0..15
    const int tx  = tid & 15;          // 0..15

    float acc[4][4];
#pragma unroll
    for (int r = 0; r < 4; r++)
#pragma unroll
        for (int c = 0; c < 4; c++) acc[r][c] = 0.f;

    for (int c0 = 0; c0 < EMB; c0 += 64) {
        // Cooperative load: 64 rows x 16 float4 each for X and W.
#pragma unroll
        for (int i = tid; i < 64 * 16; i += 256) {
            const int r  = i >> 4;
            const int cg = i & 15;
            float4 v = *(const float4*)(x + (size_t)(mblk * 64 + r) * EMB + c0 + cg * 4);
            Xs[r][cg * 4 + 0] = v.x; Xs[r][cg * 4 + 1] = v.y;
            Xs[r][cg * 4 + 2] = v.z; Xs[r][cg * 4 + 3] = v.w;
            float4 w = *(const float4*)(W + (size_t)r * EMB + c0 + cg * 4);
            Ws[r][cg * 4 + 0] = w.x; Ws[r][cg * 4 + 1] = w.y;
            Ws[r][cg * 4 + 2] = w.z; Ws[r][cg * 4 + 3] = w.w;
        }
        __syncthreads();

#pragma unroll 16
        for (int kk = 0; kk < 64; kk++) {
            float a[4], b[4];
#pragma unroll
            for (int r = 0; r < 4; r++) a[r] = Xs[ty * 4 + r][kk];
#pragma unroll
            for (int c = 0; c < 4; c++) b[c] = Ws[tx * 4 + c][kk];
#pragma unroll
            for (int r = 0; r < 4; r++)
#pragma unroll
                for (int c = 0; c < 4; c++) acc[r][c] += a[r] * b[c];
        }
        __syncthreads();
    }

#pragma unroll
    for (int r = 0; r < 4; r++) {
        const int m = mblk * 64 + ty * 4 + r;
#pragma unroll
        for (int c = 0; c < 4; c++)
            out[(size_t)m * HS + tx * 4 + c] = acc[r][c];
    }
}

// ---------------------------------------------------------------------------
// Kernel B: causal flash attention.  One CTA per (q-block of 64, batch).
// BM = BN = 64, HS = 64.  Online softmax; P staged through smem for PV GEMM.
// ---------------------------------------------------------------------------
#define SM_STRIDE 65
#define SMEM_BYTES (4 * 64 * SM_STRIDE * (int)sizeof(float))

__global__ __launch_bounds__(256) void flash_kernel(float* __restrict__ out)
{
    extern __shared__ float sm[];
    float (*Qs)[SM_STRIDE] = (float(*)[SM_STRIDE])(sm);
    float (*Ks)[SM_STRIDE] = (float(*)[SM_STRIDE])(sm + 64 * SM_STRIDE);
    float (*Vs)[SM_STRIDE] = (float(*)[SM_STRIDE])(sm + 2 * 64 * SM_STRIDE);
    float (*Ps)[SM_STRIDE] = (float(*)[SM_STRIDE])(sm + 3 * 64 * SM_STRIDE);

    const int qblk = blockIdx.x;   // 0..31
    const int b    = blockIdx.y;   // 0..3
    const int tid  = threadIdx.x;
    const int ty   = tid >> 4;
    const int tx   = tid & 15;

    const float* Qp = g_Q + (size_t)b * SEQ * HS;
    const float* Kp = g_K + (size_t)b * SEQ * HS;
    const float* Vp = g_V + (size_t)b * SEQ * HS;

    // Load Q tile (rows qblk*64 .. +63).
#pragma unroll
    for (int i = tid; i < 64 * 16; i += 256) {
        const int r  = i >> 4;
        const int cg = i & 15;
        float4 v = *(const float4*)(Qp + (size_t)(qblk * 64 + r) * HS + cg * 4);
        Qs[r][cg * 4 + 0] = v.x; Qs[r][cg * 4 + 1] = v.y;
        Qs[r][cg * 4 + 2] = v.z; Qs[r][cg * 4 + 3] = v.w;
    }

    float m_i[4], l_i[4], o[4][4];
#pragma unroll
    for (int r = 0; r < 4; r++) {
        m_i[r] = -1e30f;
        l_i[r] = 0.f;
#pragma unroll
        for (int c = 0; c < 4; c++) o[r][c] = 0.f;
    }
    __syncthreads();

    const float scale = 0.125f;    // HS^-0.5

    for (int j = 0; j <= qblk; j++) {
        // Load K and V tiles (key rows j*64 .. +63).
#pragma unroll
        for (int i = tid; i < 64 * 16; i += 256) {
            const int r  = i >> 4;
            const int cg = i & 15;
            float4 kv = *(const float4*)(Kp + (size_t)(j * 64 + r) * HS + cg * 4);
            Ks[r][cg * 4 + 0] = kv.x; Ks[r][cg * 4 + 1] = kv.y;
            Ks[r][cg * 4 + 2] = kv.z; Ks[r][cg * 4 + 3] = kv.w;
            float4 vv = *(const float4*)(Vp + (size_t)(j * 64 + r) * HS + cg * 4);
            Vs[r][cg * 4 + 0] = vv.x; Vs[r][cg * 4 + 1] = vv.y;
            Vs[r][cg * 4 + 2] = vv.z; Vs[r][cg * 4 + 3] = vv.w;
        }
        __syncthreads();

        // S = Q K^T  (4x4 per thread over HS=64)
        float s[4][4];
#pragma unroll
        for (int r = 0; r < 4; r++)
#pragma unroll
            for (int c = 0; c < 4; c++) s[r][c] = 0.f;

#pragma unroll 16
        for (int kk = 0; kk < 64; kk++) {
            float a[4], bb[4];
#pragma unroll
            for (int r = 0; r < 4; r++) a[r] = Qs[ty * 4 + r][kk];
#pragma unroll
            for (int c = 0; c < 4; c++) bb[c] = Ks[tx * 4 + c][kk];
#pragma unroll
            for (int r = 0; r < 4; r++)
#pragma unroll
                for (int c = 0; c < 4; c++) s[r][c] += a[r] * bb[c];
        }

        // Scale + causal mask (only the diagonal tile needs masking).
        const bool diag = (j == qblk);
#pragma unroll
        for (int r = 0; r < 4; r++) {
#pragma unroll
            for (int c = 0; c < 4; c++) {
                float v = s[r][c] * scale;
                if (diag && (tx * 4 + c) > (ty * 4 + r)) v = -1e30f;
                s[r][c] = v;
            }
        }

        // Row max across this tile (reduce over tx lanes: xor 1,2,4,8).
        float rmax[4];
#pragma unroll
        for (int r = 0; r < 4; r++) {
            float mv = fmaxf(fmaxf(s[r][0], s[r][1]), fmaxf(s[r][2], s[r][3]));
#pragma unroll
            for (int off = 1; off < 16; off <<= 1)
                mv = fmaxf(mv, __shfl_xor_sync(0xffffffffu, mv, off));
            rmax[r] = mv;
        }

        // Online softmax update.
        float alpha[4];
#pragma unroll
        for (int r = 0; r < 4; r++) {
            const float mnew = fmaxf(m_i[r], rmax[r]);
            alpha[r] = __expf(m_i[r] - mnew);
            m_i[r]   = mnew;
        }

        float rsum[4];
#pragma unroll
        for (int r = 0; r < 4; r++) {
            float sum = 0.f;
#pragma unroll
            for (int c = 0; c < 4; c++) {
                const float p = __expf(s[r][c] - m_i[r]);
                s[r][c] = p;
                sum += p;
            }
#pragma unroll
            for (int off = 1; off < 16; off <<= 1)
                sum += __shfl_xor_sync(0xffffffffu, sum, off);
            rsum[r] = sum;
        }

#pragma unroll
        for (int r = 0; r < 4; r++) {
            l_i[r] = l_i[r] * alpha[r] + rsum[r];
#pragma unroll
            for (int c = 0; c < 4; c++) o[r][c] *= alpha[r];
        }

        // Stage P to smem for the PV GEMM.
#pragma unroll
        for (int r = 0; r < 4; r++)
#pragma unroll
            for (int c = 0; c < 4; c++)
                Ps[ty * 4 + r][tx * 4 + c] = s[r][c];
        __syncthreads();

        // O += P V   (inner dim = 64 keys)
#pragma unroll 16
        for (int kk = 0; kk < 64; kk++) {
            float p[4], vv[4];
#pragma unroll
            for (int r = 0; r < 4; r++) p[r] = Ps[ty * 4 + r][kk];
#pragma unroll
            for (int c = 0; c < 4; c++) vv[c] = Vs[kk][tx * 4 + c];
#pragma unroll
            for (int r = 0; r < 4; r++)
#pragma unroll
                for (int c = 0; c < 4; c++) o[r][c] += p[r] * vv[c];
        }
        __syncthreads();   // before next tile overwrites Ks/Vs/Ps
    }

    // Final normalize + store.
#pragma unroll
    for (int r = 0; r < 4; r++) {
        const int q = qblk * 64 + ty * 4 + r;
        const float inv_l = 1.f / l_i[r];
#pragma unroll
        for (int c = 0; c < 4; c++)
            out[((size_t)b * SEQ + q) * HS + tx * 4 + c] = o[r][c] * inv_l;
    }
}

// ---------------------------------------------------------------------------

extern "C" void kernel_launch(void* const* d_in, const int* in_sizes, int n_in,
                              void* d_out, int out_size)
{
    const float* x  = (const float*)d_in[0];
    const float* Wq = (const float*)d_in[1];
    const float* Wk = (const float*)d_in[2];
    const float* Wv = (const float*)d_in[3];
    float* out      = (float*)d_out;

    (void)in_sizes; (void)n_in; (void)out_size;

    cudaFuncSetAttribute(flash_kernel,
                         cudaFuncAttributeMaxDynamicSharedMemorySize,
                         SMEM_BYTES);

    proj_kernel<<<dim3(BATCH * SEQ / 64, 3), 256>>>(x, Wq, Wk, Wv);
    flash_kernel<<<dim3(SEQ / 64, BATCH), 256, SMEM_BYTES>>>(out);
}

// round 3
// speedup vs baseline: 1.8839x; 1.8839x over previous
#include <cuda_runtime.h>
#include <cuda_bf16.h>
#include <cstdint>

#define BATCH 4
#define SEQ   2048
#define EMB   1024
#define HS    64
#define MROWS (BATCH * SEQ)     // 8192
#define NCOMB 192               // Wq | Wk | Wv stacked

// ---------------------------------------------------------------------------
// Device scratch (no allocations allowed)
// ---------------------------------------------------------------------------
__device__ float g_Q[MROWS * HS];
__device__ float g_K[MROWS * HS];
__device__ float g_V[MROWS * HS];
__device__ float g_Opart[2][MROWS * HS];
__device__ float g_mpart[2][MROWS];
__device__ float g_lpart[2][MROWS];

// ---------------------------------------------------------------------------
// Helpers
// ---------------------------------------------------------------------------
static __device__ __forceinline__ unsigned smem_u32(const void* p) {
    unsigned a;
    asm("{ .reg .u64 t; cvta.to.shared.u64 t, %1; cvt.u32.u64 %0, t; }"
        : "=r"(a) : "l"(p));
    return a;
}

static __device__ __forceinline__ void ldm_x4(unsigned addr, unsigned r[4]) {
    asm volatile("ldmatrix.sync.aligned.m8n8.x4.shared.b16 {%0,%1,%2,%3}, [%4];"
                 : "=r"(r[0]), "=r"(r[1]), "=r"(r[2]), "=r"(r[3]) : "r"(addr));
}

static __device__ __forceinline__ void mma_bf16(float c[4], const unsigned a[4],
                                                const unsigned b[2]) {
    asm volatile(
        "mma.sync.aligned.m16n8k16.row.col.f32.bf16.bf16.f32 "
        "{%0,%1,%2,%3}, {%4,%5,%6,%7}, {%8,%9}, {%0,%1,%2,%3};"
        : "+f"(c[0]), "+f"(c[1]), "+f"(c[2]), "+f"(c[3])
        : "r"(a[0]), "r"(a[1]), "r"(a[2]), "r"(a[3]), "r"(b[0]), "r"(b[1]));
}

static __device__ __forceinline__ unsigned pack_hi(float4 v) {
    __nv_bfloat162 p0 = __halves2bfloat162(__float2bfloat16(v.x), __float2bfloat16(v.y));
    return reinterpret_cast<unsigned&>(p0);
}

// ---------------------------------------------------------------------------
// Kernel 1: combined QKV GEMM via mma.sync bf16 hi/lo (3 passes, fp32 accum).
// out[m][n] = sum_c x[m][c] * Wcomb[n][c], M=8192, N=192, K=1024.
// CTA: 64 rows x 192 cols, 256 threads (8 warps = 2m x 4n), warptile 32x48.
// Grid: 128 CTAs. fp32->bf16 hi/lo split happens during the smem fill.
// ---------------------------------------------------------------------------
#define BK 64
#define AST 72                      // smem row stride (bf16 elems): conflict-free
#define SA_ELEMS (64 * AST)
#define SB_ELEMS (192 * AST)
#define G_SMEM_BYTES ((2 * SA_ELEMS + 2 * SB_ELEMS) * 2)

__global__ __launch_bounds__(256) void qkv_gemm_kernel(
    const float* __restrict__ x,  const float* __restrict__ Wq,
    const float* __restrict__ Wk, const float* __restrict__ Wv)
{
    extern __shared__ __nv_bfloat16 sm[];
    __nv_bfloat16* sAhi = sm;
    __nv_bfloat16* sAlo = sAhi + SA_ELEMS;
    __nv_bfloat16* sBhi = sAlo + SA_ELEMS;
    __nv_bfloat16* sBlo = sBhi + SB_ELEMS;

    const int tid  = threadIdx.x;
    const int wid  = tid >> 5;
    const int lane = tid & 31;
    const int wm   = wid & 1;        // 0..1  (32 rows each)
    const int wn   = wid >> 1;       // 0..3  (48 cols each)
    const int m0   = blockIdx.x * 64;

    float acc[2][6][4];
#pragma unroll
    for (int f = 0; f < 2; f++)
#pragma unroll
        for (int g = 0; g < 6; g++)
#pragma unroll
            for (int e = 0; e < 4; e++) acc[f][g][e] = 0.f;

    // ldmatrix source addresses (fixed per thread, k-chunk local)
    const unsigned sAhi_u = smem_u32(sAhi), sAlo_u = smem_u32(sAlo);
    const unsigned sBhi_u = smem_u32(sBhi), sBlo_u = smem_u32(sBlo);
    const int a_row = wm * 32 + (lane & 15);           // + f*16
    const int a_col = (lane >> 4) * 8;                 // + ks*16
    const int b_sub = lane >> 3;                       // 0..3
    const int b_row = (b_sub >> 1) * 8 + (lane & 7);   // + wn*48 + p*16
    const int b_col = (b_sub & 1) * 8;                 // + ks*16

    for (int c0 = 0; c0 < EMB; c0 += BK) {
        __syncthreads();
        // Fill A (64 rows x 64 k): 1024 float4 -> hi/lo bf16
#pragma unroll
        for (int i = tid; i < 64 * 16; i += 256) {
            const int row = i >> 4, u = i & 15;
            float4 v = *(const float4*)(x + (size_t)(m0 + row) * EMB + c0 + u * 4);
            float4 h;
            h.x = __bfloat162float(__float2bfloat16(v.x));
            h.y = __bfloat162float(__float2bfloat16(v.y));
            h.z = __bfloat162float(__float2bfloat16(v.z));
            h.w = __bfloat162float(__float2bfloat16(v.w));
            uint2 hp, lp;
            hp.x = pack_hi(v);
            hp.y = pack_hi(make_float4(v.z, v.w, 0, 0));
            float4 l = make_float4(v.x - h.x, v.y - h.y, v.z - h.z, v.w - h.w);
            lp.x = pack_hi(l);
            lp.y = pack_hi(make_float4(l.z, l.w, 0, 0));
            *(uint2*)(sAhi + row * AST + u * 4) = hp;
            *(uint2*)(sAlo + row * AST + u * 4) = lp;
        }
        // Fill B (192 rows x 64 k)
#pragma unroll
        for (int i = tid; i < 192 * 16; i += 256) {
            const int row = i >> 4, u = i & 15;
            const float* src = (row < 64)  ? (Wq + (size_t)row * EMB)
                             : (row < 128) ? (Wk + (size_t)(row - 64) * EMB)
                                           : (Wv + (size_t)(row - 128) * EMB);
            float4 v = *(const float4*)(src + c0 + u * 4);
            float4 h;
            h.x = __bfloat162float(__float2bfloat16(v.x));
            h.y = __bfloat162float(__float2bfloat16(v.y));
            h.z = __bfloat162float(__float2bfloat16(v.z));
            h.w = __bfloat162float(__float2bfloat16(v.w));
            uint2 hp, lp;
            hp.x = pack_hi(v);
            hp.y = pack_hi(make_float4(v.z, v.w, 0, 0));
            float4 l = make_float4(v.x - h.x, v.y - h.y, v.z - h.z, v.w - h.w);
            lp.x = pack_hi(l);
            lp.y = pack_hi(make_float4(l.z, l.w, 0, 0));
            *(uint2*)(sBhi + row * AST + u * 4) = hp;
            *(uint2*)(sBlo + row * AST + u * 4) = lp;
        }
        __syncthreads();

#pragma unroll
        for (int ks = 0; ks < 4; ks++) {
            unsigned ah[2][4], al[2][4], bh[6][2], bl[6][2];
#pragma unroll
            for (int f = 0; f < 2; f++) {
                const unsigned off =
                    ((a_row + f * 16) * AST + a_col + ks * 16) * 2;
                ldm_x4(sAhi_u + off, ah[f]);
                ldm_x4(sAlo_u + off, al[f]);
            }
#pragma unroll
            for (int p = 0; p < 3; p++) {
                const unsigned off =
                    ((wn * 48 + p * 16 + b_row) * AST + b_col + ks * 16) * 2;
                unsigned t[4];
                ldm_x4(sBhi_u + off, t);
                bh[p * 2][0] = t[0]; bh[p * 2][1] = t[1];
                bh[p * 2 + 1][0] = t[2]; bh[p * 2 + 1][1] = t[3];
                ldm_x4(sBlo_u + off, t);
                bl[p * 2][0] = t[0]; bl[p * 2][1] = t[1];
                bl[p * 2 + 1][0] = t[2]; bl[p * 2 + 1][1] = t[3];
            }
#pragma unroll
            for (int f = 0; f < 2; f++)
#pragma unroll
                for (int g = 0; g < 6; g++) {
                    mma_bf16(acc[f][g], ah[f], bh[g]);
                    mma_bf16(acc[f][g], ah[f], bl[g]);
                    mma_bf16(acc[f][g], al[f], bh[g]);
                }
        }
    }

    // Epilogue: fragment layout -> g_Q / g_K / g_V (fp32)
#pragma unroll
    for (int g = 0; g < 6; g++) {
        const int nblk = wn * 48 + g * 8;
        float* base = (nblk < 64) ? g_Q : ((nblk < 128) ? g_K : g_V);
        const int coff = (nblk & 63) + (lane & 3) * 2;
#pragma unroll
        for (int f = 0; f < 2; f++) {
            const int row = m0 + wm * 32 + f * 16 + (lane >> 2);
            float2 v0 = make_float2(acc[f][g][0], acc[f][g][1]);
            float2 v1 = make_float2(acc[f][g][2], acc[f][g][3]);
            *(float2*)(base + (size_t)row * HS + coff)       = v0;
            *(float2*)(base + (size_t)(row + 8) * HS + coff) = v1;
        }
    }
}

// ---------------------------------------------------------------------------
// Kernel 2: causal flash attention, split-K over key tiles (2 CTAs / q-block).
// BM = BN = 64, 256 threads, 4x4 register tiles, fp32.
// ---------------------------------------------------------------------------
#define SM_STRIDE 65
#define SMEM_BYTES (4 * 64 * SM_STRIDE * (int)sizeof(float))

__global__ __launch_bounds__(256) void flash_kernel()
{
    extern __shared__ float smf[];
    float (*Qs)[SM_STRIDE] = (float(*)[SM_STRIDE])(smf);
    float (*Ks)[SM_STRIDE] = (float(*)[SM_STRIDE])(smf + 64 * SM_STRIDE);
    float (*Vs)[SM_STRIDE] = (float(*)[SM_STRIDE])(smf + 2 * 64 * SM_STRIDE);
    float (*Ps)[SM_STRIDE] = (float(*)[SM_STRIDE])(smf + 3 * 64 * SM_STRIDE);

    const int bx   = blockIdx.x;          // 0..255
    const int half = bx & 1;
    const int w    = bx >> 1;             // 0..127
    const int b    = w & 3;
    const int qblk = 31 - (w >> 2);       // heavy-first

    const int nt = qblk + 1;              // total key tiles
    const int n0 = (nt + 1) >> 1;
    const int jb = half ? n0 : 0;
    const int je = half ? nt : n0;

    const int tid = threadIdx.x;
    const int ty  = tid >> 4;
    const int tx  = tid & 15;

    const float* Qp = g_Q + (size_t)b * SEQ * HS;
    const float* Kp = g_K + (size_t)b * SEQ * HS;
    const float* Vp = g_V + (size_t)b * SEQ * HS;

#pragma unroll
    for (int i = tid; i < 64 * 16; i += 256) {
        const int r = i >> 4, cg = i & 15;
        float4 v = *(const float4*)(Qp + (size_t)(qblk * 64 + r) * HS + cg * 4);
        Qs[r][cg * 4 + 0] = v.x; Qs[r][cg * 4 + 1] = v.y;
        Qs[r][cg * 4 + 2] = v.z; Qs[r][cg * 4 + 3] = v.w;
    }

    float m_i[4], l_i[4], o[4][4];
#pragma unroll
    for (int r = 0; r < 4; r++) {
        m_i[r] = -1e30f; l_i[r] = 0.f;
#pragma unroll
        for (int c = 0; c < 4; c++) o[r][c] = 0.f;
    }
    __syncthreads();

    const float scale = 0.125f;

    for (int j = jb; j < je; j++) {
#pragma unroll
        for (int i = tid; i < 64 * 16; i += 256) {
            const int r = i >> 4, cg = i & 15;
            float4 kv = *(const float4*)(Kp + (size_t)(j * 64 + r) * HS + cg * 4);
            Ks[r][cg * 4 + 0] = kv.x; Ks[r][cg * 4 + 1] = kv.y;
            Ks[r][cg * 4 + 2] = kv.z; Ks[r][cg * 4 + 3] = kv.w;
            float4 vv = *(const float4*)(Vp + (size_t)(j * 64 + r) * HS + cg * 4);
            Vs[r][cg * 4 + 0] = vv.x; Vs[r][cg * 4 + 1] = vv.y;
            Vs[r][cg * 4 + 2] = vv.z; Vs[r][cg * 4 + 3] = vv.w;
        }
        __syncthreads();

        float s[4][4];
#pragma unroll
        for (int r = 0; r < 4; r++)
#pragma unroll
            for (int c = 0; c < 4; c++) s[r][c] = 0.f;

#pragma unroll 16
        for (int kk = 0; kk < 64; kk++) {
            float a[4], bb[4];
#pragma unroll
            for (int r = 0; r < 4; r++) a[r] = Qs[ty * 4 + r][kk];
#pragma unroll
            for (int c = 0; c < 4; c++) bb[c] = Ks[tx * 4 + c][kk];
#pragma unroll
            for (int r = 0; r < 4; r++)
#pragma unroll
                for (int c = 0; c < 4; c++) s[r][c] += a[r] * bb[c];
        }

        const bool diag = (j == qblk);
#pragma unroll
        for (int r = 0; r < 4; r++)
#pragma unroll
            for (int c = 0; c < 4; c++) {
                float v = s[r][c] * scale;
                if (diag && (tx * 4 + c) > (ty * 4 + r)) v = -1e30f;
                s[r][c] = v;
            }

        float rmax[4];
#pragma unroll
        for (int r = 0; r < 4; r++) {
            float mv = fmaxf(fmaxf(s[r][0], s[r][1]), fmaxf(s[r][2], s[r][3]));
#pragma unroll
            for (int off = 1; off < 16; off <<= 1)
                mv = fmaxf(mv, __shfl_xor_sync(0xffffffffu, mv, off));
            rmax[r] = mv;
        }

        float alpha[4];
#pragma unroll
        for (int r = 0; r < 4; r++) {
            const float mnew = fmaxf(m_i[r], rmax[r]);
            alpha[r] = __expf(m_i[r] - mnew);
            m_i[r]   = mnew;
        }

        float rsum[4];
#pragma unroll
        for (int r = 0; r < 4; r++) {
            float sum = 0.f;
#pragma unroll
            for (int c = 0; c < 4; c++) {
                const float p = __expf(s[r][c] - m_i[r]);
                s[r][c] = p; sum += p;
            }
#pragma unroll
            for (int off = 1; off < 16; off <<= 1)
                sum += __shfl_xor_sync(0xffffffffu, sum, off);
            rsum[r] = sum;
        }

#pragma unroll
        for (int r = 0; r < 4; r++) {
            l_i[r] = l_i[r] * alpha[r] + rsum[r];
#pragma unroll
            for (int c = 0; c < 4; c++) o[r][c] *= alpha[r];
        }

#pragma unroll
        for (int r = 0; r < 4; r++)
#pragma unroll
            for (int c = 0; c < 4; c++)
                Ps[ty * 4 + r][tx * 4 + c] = s[r][c];
        __syncthreads();

#pragma unroll 16
        for (int kk = 0; kk < 64; kk++) {
            float p[4], vv[4];
#pragma unroll
            for (int r = 0; r < 4; r++) p[r] = Ps[ty * 4 + r][kk];
#pragma unroll
            for (int c = 0; c < 4; c++) vv[c] = Vs[kk][tx * 4 + c];
#pragma unroll
            for (int r = 0; r < 4; r++)
#pragma unroll
                for (int c = 0; c < 4; c++) o[r][c] += p[r] * vv[c];
        }
        __syncthreads();
    }

    // Store UNNORMALIZED partial + (m, l) for the merge kernel.
#pragma unroll
    for (int r = 0; r < 4; r++) {
        const int q = qblk * 64 + ty * 4 + r;
        const size_t gr = (size_t)b * SEQ + q;
#pragma unroll
        for (int c = 0; c < 4; c++)
            g_Opart[half][gr * HS + tx * 4 + c] = o[r][c];
        if (tx == 0) {
            g_mpart[half][gr] = m_i[r];
            g_lpart[half][gr] = l_i[r];
        }
    }
}

// ---------------------------------------------------------------------------
// Kernel 3: merge the two split-K partials.  One thread per (b, t) row.
// ---------------------------------------------------------------------------
__global__ __launch_bounds__(128) void merge_kernel(float* __restrict__ out)
{
    const int r = blockIdx.x * 128 + threadIdx.x;   // 0..8191
    const float m0 = g_mpart[0][r], m1 = g_mpart[1][r];
    const float l0 = g_lpart[0][r], l1 = g_lpart[1][r];
    const float m  = fmaxf(m0, m1);
    const float a0 = __expf(m0 - m), a1 = __expf(m1 - m);
    const float inv = 1.f / (l0 * a0 + l1 * a1);

    const float4* p0 = (const float4*)(g_Opart[0] + (size_t)r * HS);
    const float4* p1 = (const float4*)(g_Opart[1] + (size_t)r * HS);
    float4* po = (float4*)(out + (size_t)r * HS);
#pragma unroll
    for (int u = 0; u < 16; u++) {
        float4 v0 = p0[u], v1 = p1[u], w;
        w.x = (v0.x * a0 + v1.x * a1) * inv;
        w.y = (v0.y * a0 + v1.y * a1) * inv;
        w.z = (v0.z * a0 + v1.z * a1) * inv;
        w.w = (v0.w * a0 + v1.w * a1) * inv;
        po[u] = w;
    }
}

// ---------------------------------------------------------------------------

extern "C" void kernel_launch(void* const* d_in, const int* in_sizes, int n_in,
                              void* d_out, int out_size)
{
    const float* x  = (const float*)d_in[0];
    const float* Wq = (const float*)d_in[1];
    const float* Wk = (const float*)d_in[2];
    const float* Wv = (const float*)d_in[3];
    float* out      = (float*)d_out;
    (void)in_sizes; (void)n_in; (void)out_size;

    cudaFuncSetAttribute(qkv_gemm_kernel,
                         cudaFuncAttributeMaxDynamicSharedMemorySize, G_SMEM_BYTES);
    cudaFuncSetAttribute(flash_kernel,
                         cudaFuncAttributeMaxDynamicSharedMemorySize, SMEM_BYTES);

    qkv_gemm_kernel<<<MROWS / 64, 256, G_SMEM_BYTES>>>(x, Wq, Wk, Wv);
    flash_kernel<<<256, 256, SMEM_BYTES>>>();
    merge_kernel<<<MROWS / 128, 128>>>(out);
}

// round 4
// speedup vs baseline: 3.5520x; 1.8855x over previous
#include <cuda_runtime.h>
#include <cuda_bf16.h>
#include <cstdint>

#define BATCH 4
#define SEQ   2048
#define EMB   1024
#define HS    64
#define MROWS (BATCH * SEQ)     // 8192
#define NCOMB 192               // Wq | Wk | Wv stacked

// ---------------------------------------------------------------------------
// Device scratch (no allocations allowed)
// ---------------------------------------------------------------------------
__device__ __nv_bfloat16 g_Whi[NCOMB * EMB];
__device__ __nv_bfloat16 g_Wlo[NCOMB * EMB];
__device__ __nv_bfloat16 g_Qhi[MROWS * HS];   // pre-scaled by 0.125
__device__ __nv_bfloat16 g_Qlo[MROWS * HS];
__device__ __nv_bfloat16 g_Khi[MROWS * HS];
__device__ __nv_bfloat16 g_Klo[MROWS * HS];
__device__ __nv_bfloat16 g_Vhi[MROWS * HS];
__device__ __nv_bfloat16 g_Vlo[MROWS * HS];
__device__ float g_Opart[2][MROWS * HS];
__device__ float g_mpart[2][MROWS];
__device__ float g_lpart[2][MROWS];

// ---------------------------------------------------------------------------
// Helpers
// ---------------------------------------------------------------------------
static __device__ __forceinline__ unsigned smem_u32(const void* p) {
    unsigned a;
    asm("{ .reg .u64 t; cvta.to.shared.u64 t, %1; cvt.u32.u64 %0, t; }"
        : "=r"(a) : "l"(p));
    return a;
}
static __device__ __forceinline__ void ldm_x4(unsigned addr, unsigned r[4]) {
    asm volatile("ldmatrix.sync.aligned.m8n8.x4.shared.b16 {%0,%1,%2,%3}, [%4];"
                 : "=r"(r[0]), "=r"(r[1]), "=r"(r[2]), "=r"(r[3]) : "r"(addr));
}
static __device__ __forceinline__ void ldm_x4t(unsigned addr, unsigned r[4]) {
    asm volatile("ldmatrix.sync.aligned.m8n8.x4.trans.shared.b16 {%0,%1,%2,%3}, [%4];"
                 : "=r"(r[0]), "=r"(r[1]), "=r"(r[2]), "=r"(r[3]) : "r"(addr));
}
static __device__ __forceinline__ void mma_bf16(float c[4], const unsigned a[4],
                                                const unsigned b[2]) {
    asm volatile(
        "mma.sync.aligned.m16n8k16.row.col.f32.bf16.bf16.f32 "
        "{%0,%1,%2,%3}, {%4,%5,%6,%7}, {%8,%9}, {%0,%1,%2,%3};"
        : "+f"(c[0]), "+f"(c[1]), "+f"(c[2]), "+f"(c[3])
        : "r"(a[0]), "r"(a[1]), "r"(a[2]), "r"(a[3]), "r"(b[0]), "r"(b[1]));
}
static __device__ __forceinline__ unsigned pack_bf2(float a, float b) {
    __nv_bfloat162 t = __halves2bfloat162(__float2bfloat16(a), __float2bfloat16(b));
    return reinterpret_cast<unsigned&>(t);
}
static __device__ __forceinline__ void split_hl(float v0, float v1,
                                                unsigned& hi, unsigned& lo) {
    __nv_bfloat16 h0 = __float2bfloat16(v0), h1 = __float2bfloat16(v1);
    __nv_bfloat162 h = __halves2bfloat162(h0, h1);
    __nv_bfloat162 l = __halves2bfloat162(
        __float2bfloat16(v0 - __bfloat162float(h0)),
        __float2bfloat16(v1 - __bfloat162float(h1)));
    hi = reinterpret_cast<unsigned&>(h);
    lo = reinterpret_cast<unsigned&>(l);
}

// ---------------------------------------------------------------------------
// Kernel 0: W -> bf16 hi/lo (once; removes redundant per-CTA conversion)
// ---------------------------------------------------------------------------
__global__ __launch_bounds__(256) void wconv_kernel(
    const float* __restrict__ Wq, const float* __restrict__ Wk,
    const float* __restrict__ Wv)
{
    const int i = blockIdx.x * 256 + threadIdx.x;   // float4 index
    if (i >= NCOMB * EMB / 4) return;
    const int e = i * 4, row = e >> 10, col = e & 1023;
    const float* src = (row < 64)  ? (Wq + (size_t)row * EMB)
                     : (row < 128) ? (Wk + (size_t)(row - 64) * EMB)
                                   : (Wv + (size_t)(row - 128) * EMB);
    float4 v = *(const float4*)(src + col);
    uint2 hp, lp;
    split_hl(v.x, v.y, hp.x, lp.x);
    split_hl(v.z, v.w, hp.y, lp.y);
    ((uint2*)g_Whi)[i] = hp;
    ((uint2*)g_Wlo)[i] = lp;
}

// ---------------------------------------------------------------------------
// Kernel 1: combined QKV GEMM via mma.sync bf16 hi/lo (3 passes, fp32 accum).
// CTA: 64 rows x 192 cols, 256 threads (2m x 4n warps), writes bf16 hi/lo.
// ---------------------------------------------------------------------------
#define BK 64
#define AST 72
#define SA_ELEMS (64 * AST)
#define SB_ELEMS (192 * AST)
#define G_SMEM_BYTES ((2 * SA_ELEMS + 2 * SB_ELEMS) * 2)

__global__ __launch_bounds__(256) void qkv_gemm_kernel(const float* __restrict__ x)
{
    extern __shared__ __nv_bfloat16 sm[];
    __nv_bfloat16* sAhi = sm;
    __nv_bfloat16* sAlo = sAhi + SA_ELEMS;
    __nv_bfloat16* sBhi = sAlo + SA_ELEMS;
    __nv_bfloat16* sBlo = sBhi + SB_ELEMS;

    const int tid  = threadIdx.x;
    const int wid  = tid >> 5;
    const int lane = tid & 31;
    const int wm   = wid & 1;
    const int wn   = wid >> 1;
    const int m0   = blockIdx.x * 64;

    float acc[2][6][4];
#pragma unroll
    for (int f = 0; f < 2; f++)
#pragma unroll
        for (int g = 0; g < 6; g++)
#pragma unroll
            for (int e = 0; e < 4; e++) acc[f][g][e] = 0.f;

    const unsigned sAhi_u = smem_u32(sAhi), sAlo_u = smem_u32(sAlo);
    const unsigned sBhi_u = smem_u32(sBhi), sBlo_u = smem_u32(sBlo);
    const int a_row = wm * 32 + (lane & 15);
    const int a_col = (lane >> 4) * 8;
    const int b_sub = lane >> 3;
    const int b_row = (b_sub >> 1) * 8 + (lane & 7);
    const int b_col = (b_sub & 1) * 8;

    for (int c0 = 0; c0 < EMB; c0 += BK) {
        __syncthreads();
        // A: fused fp32 -> bf16 hi/lo
#pragma unroll
        for (int i = tid; i < 64 * 16; i += 256) {
            const int row = i >> 4, u = i & 15;
            float4 v = *(const float4*)(x + (size_t)(m0 + row) * EMB + c0 + u * 4);
            uint2 hp, lp;
            split_hl(v.x, v.y, hp.x, lp.x);
            split_hl(v.z, v.w, hp.y, lp.y);
            *(uint2*)(sAhi + row * AST + u * 4) = hp;
            *(uint2*)(sAlo + row * AST + u * 4) = lp;
        }
        // B: straight copy of precomputed hi/lo
#pragma unroll
        for (int i = tid; i < 192 * 8; i += 256) {
            const int row = i >> 3, u = i & 7;
            *(uint4*)(sBhi + row * AST + u * 8) =
                *(const uint4*)(g_Whi + (size_t)row * EMB + c0 + u * 8);
            *(uint4*)(sBlo + row * AST + u * 8) =
                *(const uint4*)(g_Wlo + (size_t)row * EMB + c0 + u * 8);
        }
        __syncthreads();

#pragma unroll
        for (int ks = 0; ks < 4; ks++) {
            unsigned ah[2][4], al[2][4], bh[6][2], bl[6][2];
#pragma unroll
            for (int f = 0; f < 2; f++) {
                const unsigned off = ((a_row + f * 16) * AST + a_col + ks * 16) * 2;
                ldm_x4(sAhi_u + off, ah[f]);
                ldm_x4(sAlo_u + off, al[f]);
            }
#pragma unroll
            for (int p = 0; p < 3; p++) {
                const unsigned off =
                    ((wn * 48 + p * 16 + b_row) * AST + b_col + ks * 16) * 2;
                unsigned t[4];
                ldm_x4(sBhi_u + off, t);
                bh[p * 2][0] = t[0]; bh[p * 2][1] = t[1];
                bh[p * 2 + 1][0] = t[2]; bh[p * 2 + 1][1] = t[3];
                ldm_x4(sBlo_u + off, t);
                bl[p * 2][0] = t[0]; bl[p * 2][1] = t[1];
                bl[p * 2 + 1][0] = t[2]; bl[p * 2 + 1][1] = t[3];
            }
#pragma unroll
            for (int f = 0; f < 2; f++)
#pragma unroll
                for (int g = 0; g < 6; g++) {
                    mma_bf16(acc[f][g], ah[f], bh[g]);
                    mma_bf16(acc[f][g], ah[f], bl[g]);
                    mma_bf16(acc[f][g], al[f], bh[g]);
                }
        }
    }

    // Epilogue: write bf16 hi/lo Q (pre-scaled), K, V
#pragma unroll
    for (int g = 0; g < 6; g++) {
        const int nblk = wn * 48 + g * 8;
        __nv_bfloat16* hb = (nblk < 64) ? g_Qhi : ((nblk < 128) ? g_Khi : g_Vhi);
        __nv_bfloat16* lb = (nblk < 64) ? g_Qlo : ((nblk < 128) ? g_Klo : g_Vlo);
        const float sc = (nblk < 64) ? 0.125f : 1.0f;
        const int coff = (nblk & 63) + (lane & 3) * 2;
#pragma unroll
        for (int f = 0; f < 2; f++) {
            const int row = m0 + wm * 32 + f * 16 + (lane >> 2);
            unsigned h0, l0, h1, l1;
            split_hl(acc[f][g][0] * sc, acc[f][g][1] * sc, h0, l0);
            split_hl(acc[f][g][2] * sc, acc[f][g][3] * sc, h1, l1);
            *(unsigned*)(hb + (size_t)row * HS + coff)       = h0;
            *(unsigned*)(lb + (size_t)row * HS + coff)       = l0;
            *(unsigned*)(hb + (size_t)(row + 8) * HS + coff) = h1;
            *(unsigned*)(lb + (size_t)(row + 8) * HS + coff) = l1;
        }
    }
}

// ---------------------------------------------------------------------------
// Kernel 2: causal flash attention on mma.sync bf16 hi/lo.
// BM=BN=64, 4 warps (128 thr), warp owns 16 rows. Split-K 2x, heavy-first.
// ---------------------------------------------------------------------------
#define FST 72
#define F_TILE (64 * FST)
#define F_SMEM_BYTES (6 * F_TILE * 2)

__global__ __launch_bounds__(128) void flash_kernel()
{
    extern __shared__ __nv_bfloat16 fs[];
    __nv_bfloat16* sQh = fs;
    __nv_bfloat16* sQl = sQh + F_TILE;
    __nv_bfloat16* sKh = sQl + F_TILE;
    __nv_bfloat16* sKl = sKh + F_TILE;
    __nv_bfloat16* sVh = sKl + F_TILE;
    __nv_bfloat16* sVl = sVh + F_TILE;

    const int bx   = blockIdx.x;
    const int half = bx & 1;
    const int widx = bx >> 1;
    const int b    = widx & 3;
    const int qblk = 31 - (widx >> 2);      // heavy-first

    const int nt = qblk + 1;
    const int n0 = (nt + 1) >> 1;
    const int jb = half ? n0 : 0;
    const int je = half ? nt : n0;

    const int tid  = threadIdx.x;
    const int w    = tid >> 5;
    const int lane = tid & 31;

    const size_t base = (size_t)b * SEQ * HS;

    // Load Q tile (hi/lo)
#pragma unroll
    for (int i = tid; i < 64 * 8; i += 128) {
        const int row = i >> 3, u = i & 7;
        const size_t gi = base + (size_t)(qblk * 64 + row) * HS + u * 8;
        *(uint4*)(sQh + row * FST + u * 8) = *(const uint4*)(g_Qhi + gi);
        *(uint4*)(sQl + row * FST + u * 8) = *(const uint4*)(g_Qlo + gi);
    }
    __syncthreads();

    // Hoist Q fragments (loop-invariant)
    const unsigned sQh_u = smem_u32(sQh), sQl_u = smem_u32(sQl);
    const unsigned sKh_u = smem_u32(sKh), sKl_u = smem_u32(sKl);
    const unsigned sVh_u = smem_u32(sVh), sVl_u = smem_u32(sVl);
    unsigned qh[4][4], ql[4][4];
    {
        const int ar = w * 16 + (lane & 15);
        const int ac = (lane >> 4) * 8;
#pragma unroll
        for (int ks = 0; ks < 4; ks++) {
            const unsigned off = (ar * FST + ks * 16 + ac) * 2;
            ldm_x4(sQh_u + off, qh[ks]);
            ldm_x4(sQl_u + off, ql[ks]);
        }
    }

    float o[8][4];
#pragma unroll
    for (int nf = 0; nf < 8; nf++)
#pragma unroll
        for (int e = 0; e < 4; e++) o[nf][e] = 0.f;
    float mA = -1e30f, mB = -1e30f, lA = 0.f, lB = 0.f;

    // ldmatrix address components
    const int b_sub = lane >> 3;
    const int kb_row = (b_sub >> 1) * 8 + (lane & 7);   // K frags (non-trans)
    const int kb_col = (b_sub & 1) * 8;
    const int vb_row = (b_sub & 1) * 8 + (lane & 7);    // V frags (trans)
    const int vb_col = (b_sub >> 1) * 8;

    for (int j = jb; j < je; j++) {
        // Fill K/V hi/lo tiles
#pragma unroll
        for (int i = tid; i < 64 * 8; i += 128) {
            const int row = i >> 3, u = i & 7;
            const size_t gi = base + (size_t)(j * 64 + row) * HS + u * 8;
            *(uint4*)(sKh + row * FST + u * 8) = *(const uint4*)(g_Khi + gi);
            *(uint4*)(sKl + row * FST + u * 8) = *(const uint4*)(g_Klo + gi);
            *(uint4*)(sVh + row * FST + u * 8) = *(const uint4*)(g_Vhi + gi);
            *(uint4*)(sVl + row * FST + u * 8) = *(const uint4*)(g_Vlo + gi);
        }
        __syncthreads();

        // S = Q K^T (hi/lo, 3 passes)
        float s[8][4];
#pragma unroll
        for (int nf = 0; nf < 8; nf++)
#pragma unroll
            for (int e = 0; e < 4; e++) s[nf][e] = 0.f;

#pragma unroll
        for (int ks = 0; ks < 4; ks++) {
            unsigned kh[8][2], kl[8][2];
#pragma unroll
            for (int np = 0; np < 4; np++) {
                const unsigned off =
                    ((np * 16 + kb_row) * FST + ks * 16 + kb_col) * 2;
                unsigned t[4];
                ldm_x4(sKh_u + off, t);
                kh[np * 2][0] = t[0]; kh[np * 2][1] = t[1];
                kh[np * 2 + 1][0] = t[2]; kh[np * 2 + 1][1] = t[3];
                ldm_x4(sKl_u + off, t);
                kl[np * 2][0] = t[0]; kl[np * 2][1] = t[1];
                kl[np * 2 + 1][0] = t[2]; kl[np * 2 + 1][1] = t[3];
            }
#pragma unroll
            for (int nf = 0; nf < 8; nf++) {
                mma_bf16(s[nf], qh[ks], kh[nf]);
                mma_bf16(s[nf], qh[ks], kl[nf]);
                mma_bf16(s[nf], ql[ks], kh[nf]);
            }
        }

        // Causal mask (diagonal tile only); Q was pre-scaled by 0.125
        if (j == qblk) {
            const int rA = w * 16 + (lane >> 2);
            const int c0 = (lane & 3) * 2;
#pragma unroll
            for (int nf = 0; nf < 8; nf++) {
                const int c = nf * 8 + c0;
                if (c > rA)         s[nf][0] = -1e30f;
                if (c + 1 > rA)     s[nf][1] = -1e30f;
                if (c > rA + 8)     s[nf][2] = -1e30f;
                if (c + 1 > rA + 8) s[nf][3] = -1e30f;
            }
        }

        // Online softmax (rows rA = w*16+(lane>>2) and rA+8)
        float tmA = -1e30f, tmB = -1e30f;
#pragma unroll
        for (int nf = 0; nf < 8; nf++) {
            tmA = fmaxf(tmA, fmaxf(s[nf][0], s[nf][1]));
            tmB = fmaxf(tmB, fmaxf(s[nf][2], s[nf][3]));
        }
#pragma unroll
        for (int off = 1; off < 4; off <<= 1) {
            tmA = fmaxf(tmA, __shfl_xor_sync(0xffffffffu, tmA, off));
            tmB = fmaxf(tmB, __shfl_xor_sync(0xffffffffu, tmB, off));
        }
        const float mnA = fmaxf(mA, tmA), mnB = fmaxf(mB, tmB);
        const float aA = __expf(mA - mnA), aB = __expf(mB - mnB);
        mA = mnA; mB = mnB;

        float sumA = 0.f, sumB = 0.f;
#pragma unroll
        for (int nf = 0; nf < 8; nf++) {
            s[nf][0] = __expf(s[nf][0] - mnA); sumA += s[nf][0];
            s[nf][1] = __expf(s[nf][1] - mnA); sumA += s[nf][1];
            s[nf][2] = __expf(s[nf][2] - mnB); sumB += s[nf][2];
            s[nf][3] = __expf(s[nf][3] - mnB); sumB += s[nf][3];
        }
#pragma unroll
        for (int off = 1; off < 4; off <<= 1) {
            sumA += __shfl_xor_sync(0xffffffffu, sumA, off);
            sumB += __shfl_xor_sync(0xffffffffu, sumB, off);
        }
        lA = lA * aA + sumA;
        lB = lB * aB + sumB;
#pragma unroll
        for (int nf = 0; nf < 8; nf++) {
            o[nf][0] *= aA; o[nf][1] *= aA;
            o[nf][2] *= aB; o[nf][3] *= aB;
        }

        // O += P V (hi/lo, 3 passes); P fragments built from S accumulators
#pragma unroll
        for (int ks = 0; ks < 4; ks++) {
            unsigned ah[4], al[4];
            split_hl(s[2 * ks][0],     s[2 * ks][1],     ah[0], al[0]);
            split_hl(s[2 * ks][2],     s[2 * ks][3],     ah[1], al[1]);
            split_hl(s[2 * ks + 1][0], s[2 * ks + 1][1], ah[2], al[2]);
            split_hl(s[2 * ks + 1][2], s[2 * ks + 1][3], ah[3], al[3]);

            unsigned vh[8][2], vl[8][2];
#pragma unroll
            for (int hp = 0; hp < 4; hp++) {
                const unsigned off =
                    ((ks * 16 + vb_row) * FST + hp * 16 + vb_col) * 2;
                unsigned t[4];
                ldm_x4t(sVh_u + off, t);
                vh[hp * 2][0] = t[0]; vh[hp * 2][1] = t[1];
                vh[hp * 2 + 1][0] = t[2]; vh[hp * 2 + 1][1] = t[3];
                ldm_x4t(sVl_u + off, t);
                vl[hp * 2][0] = t[0]; vl[hp * 2][1] = t[1];
                vl[hp * 2 + 1][0] = t[2]; vl[hp * 2 + 1][1] = t[3];
            }
#pragma unroll
            for (int nf = 0; nf < 8; nf++) {
                mma_bf16(o[nf], ah, vh[nf]);
                mma_bf16(o[nf], ah, vl[nf]);
                mma_bf16(o[nf], al, vh[nf]);
            }
        }
        __syncthreads();
    }

    // Store unnormalized partial + (m, l)
    const int rA = qblk * 64 + w * 16 + (lane >> 2);
    const size_t grA = (size_t)b * SEQ + rA;
    const size_t grB = grA + 8;
    const int c0 = (lane & 3) * 2;
#pragma unroll
    for (int nf = 0; nf < 8; nf++) {
        const int c = nf * 8 + c0;
        *(float2*)(&g_Opart[half][grA * HS + c]) = make_float2(o[nf][0], o[nf][1]);
        *(float2*)(&g_Opart[half][grB * HS + c]) = make_float2(o[nf][2], o[nf][3]);
    }
    if ((lane & 3) == 0) {
        g_mpart[half][grA] = mA; g_lpart[half][grA] = lA;
        g_mpart[half][grB] = mB; g_lpart[half][grB] = lB;
    }
}

// ---------------------------------------------------------------------------
// Kernel 3: merge split-K partials
// ---------------------------------------------------------------------------
__global__ __launch_bounds__(128) void merge_kernel(float* __restrict__ out)
{
    const int r = blockIdx.x * 128 + threadIdx.x;
    const float m0 = g_mpart[0][r], m1 = g_mpart[1][r];
    const float l0 = g_lpart[0][r], l1 = g_lpart[1][r];
    const float m  = fmaxf(m0, m1);
    const float a0 = __expf(m0 - m), a1 = __expf(m1 - m);
    const float inv = 1.f / (l0 * a0 + l1 * a1);

    const float4* p0 = (const float4*)(g_Opart[0] + (size_t)r * HS);
    const float4* p1 = (const float4*)(g_Opart[1] + (size_t)r * HS);
    float4* po = (float4*)(out + (size_t)r * HS);
#pragma unroll
    for (int u = 0; u < 16; u++) {
        float4 v0 = p0[u], v1 = p1[u], w;
        w.x = (v0.x * a0 + v1.x * a1) * inv;
        w.y = (v0.y * a0 + v1.y * a1) * inv;
        w.z = (v0.z * a0 + v1.z * a1) * inv;
        w.w = (v0.w * a0 + v1.w * a1) * inv;
        po[u] = w;
    }
}

// ---------------------------------------------------------------------------

extern "C" void kernel_launch(void* const* d_in, const int* in_sizes, int n_in,
                              void* d_out, int out_size)
{
    const float* x  = (const float*)d_in[0];
    const float* Wq = (const float*)d_in[1];
    const float* Wk = (const float*)d_in[2];
    const float* Wv = (const float*)d_in[3];
    float* out      = (float*)d_out;
    (void)in_sizes; (void)n_in; (void)out_size;

    cudaFuncSetAttribute(qkv_gemm_kernel,
                         cudaFuncAttributeMaxDynamicSharedMemorySize, G_SMEM_BYTES);
    cudaFuncSetAttribute(flash_kernel,
                         cudaFuncAttributeMaxDynamicSharedMemorySize, F_SMEM_BYTES);

    wconv_kernel<<<(NCOMB * EMB / 4 + 255) / 256, 256>>>(Wq, Wk, Wv);
    qkv_gemm_kernel<<<MROWS / 64, 256, G_SMEM_BYTES>>>(x);
    flash_kernel<<<256, 128, F_SMEM_BYTES>>>();
    merge_kernel<<<MROWS / 128, 128>>>(out);
}

// round 5
// speedup vs baseline: 4.0394x; 1.1372x over previous
#include <cuda_runtime.h>
#include <cuda_bf16.h>
#include <cstdint>

#define BATCH 4
#define SEQ   2048
#define EMB   1024
#define HS    64
#define MROWS (BATCH * SEQ)     // 8192
#define NCOMB 192               // Wq | Wk | Wv stacked

// Q pre-scale: HS^-0.5 * log2(e)  (softmax done in exp2 domain)
#define QSCALE 0.180336880111f

// ---------------------------------------------------------------------------
// Device scratch (no allocations allowed)
// ---------------------------------------------------------------------------
__device__ __nv_bfloat16 g_Whi[NCOMB * EMB];
__device__ __nv_bfloat16 g_Wlo[NCOMB * EMB];
__device__ __nv_bfloat16 g_Qhi[MROWS * HS];   // pre-scaled by QSCALE
__device__ __nv_bfloat16 g_Qlo[MROWS * HS];
__device__ __nv_bfloat16 g_Khi[MROWS * HS];
__device__ __nv_bfloat16 g_Klo[MROWS * HS];
__device__ __nv_bfloat16 g_Vhi[MROWS * HS];
__device__ __nv_bfloat16 g_Vlo[MROWS * HS];
__device__ float g_Opart[4][MROWS * HS];
__device__ float g_mpart[4][MROWS];
__device__ float g_lpart[4][MROWS];

// ---------------------------------------------------------------------------
// Helpers
// ---------------------------------------------------------------------------
static __device__ __forceinline__ unsigned smem_u32(const void* p) {
    unsigned a;
    asm("{ .reg .u64 t; cvta.to.shared.u64 t, %1; cvt.u32.u64 %0, t; }"
        : "=r"(a) : "l"(p));
    return a;
}
static __device__ __forceinline__ void ldm_x4(unsigned addr, unsigned r[4]) {
    asm volatile("ldmatrix.sync.aligned.m8n8.x4.shared.b16 {%0,%1,%2,%3}, [%4];"
                 : "=r"(r[0]), "=r"(r[1]), "=r"(r[2]), "=r"(r[3]) : "r"(addr));
}
static __device__ __forceinline__ void ldm_x4t(unsigned addr, unsigned r[4]) {
    asm volatile("ldmatrix.sync.aligned.m8n8.x4.trans.shared.b16 {%0,%1,%2,%3}, [%4];"
                 : "=r"(r[0]), "=r"(r[1]), "=r"(r[2]), "=r"(r[3]) : "r"(addr));
}
static __device__ __forceinline__ void mma_bf16(float c[4], const unsigned a[4],
                                                const unsigned b[2]) {
    asm volatile(
        "mma.sync.aligned.m16n8k16.row.col.f32.bf16.bf16.f32 "
        "{%0,%1,%2,%3}, {%4,%5,%6,%7}, {%8,%9}, {%0,%1,%2,%3};"
        : "+f"(c[0]), "+f"(c[1]), "+f"(c[2]), "+f"(c[3])
        : "r"(a[0]), "r"(a[1]), "r"(a[2]), "r"(a[3]), "r"(b[0]), "r"(b[1]));
}
static __device__ __forceinline__ void split_hl(float v0, float v1,
                                                unsigned& hi, unsigned& lo) {
    __nv_bfloat16 h0 = __float2bfloat16(v0), h1 = __float2bfloat16(v1);
    __nv_bfloat162 h = __halves2bfloat162(h0, h1);
    __nv_bfloat162 l = __halves2bfloat162(
        __float2bfloat16(v0 - __bfloat162float(h0)),
        __float2bfloat16(v1 - __bfloat162float(h1)));
    hi = reinterpret_cast<unsigned&>(h);
    lo = reinterpret_cast<unsigned&>(l);
}
#define CP_ASYNC16(dst, src) \
    asm volatile("cp.async.cg.shared.global [%0], [%1], 16;" :: "r"(dst), "l"(src))
#define CP_COMMIT() asm volatile("cp.async.commit_group;")

// ---------------------------------------------------------------------------
// Kernel 0: W -> bf16 hi/lo (once)
// ---------------------------------------------------------------------------
__global__ __launch_bounds__(256) void wconv_kernel(
    const float* __restrict__ Wq, const float* __restrict__ Wk,
    const float* __restrict__ Wv)
{
    const int i = blockIdx.x * 256 + threadIdx.x;
    if (i >= NCOMB * EMB / 4) return;
    const int e = i * 4, row = e >> 10, col = e & 1023;
    const float* src = (row < 64)  ? (Wq + (size_t)row * EMB)
                     : (row < 128) ? (Wk + (size_t)(row - 64) * EMB)
                                   : (Wv + (size_t)(row - 128) * EMB);
    float4 v = *(const float4*)(src + col);
    uint2 hp, lp;
    split_hl(v.x, v.y, hp.x, lp.x);
    split_hl(v.z, v.w, hp.y, lp.y);
    ((uint2*)g_Whi)[i] = hp;
    ((uint2*)g_Wlo)[i] = lp;
}

// ---------------------------------------------------------------------------
// Kernel 1: combined QKV GEMM, mma.sync bf16 hi/lo, software-pipelined:
//   - B tiles double-buffered via cp.async
//   - A chunk register-prefetched one compute phase ahead
// CTA: 64 rows x 192 cols, 256 threads (2m x 4n warps). Grid 128.
// ---------------------------------------------------------------------------
#define AST 72
// smem byte offsets
#define A_HI_OFF 0
#define A_LO_OFF 9216
#define B_OFF    18432
#define B_BUF_BYTES 55296          // hi + lo, one stage (192*72*2 each)
#define B_HL_BYTES  27648
#define G_SMEM_BYTES (18432 + 2 * B_BUF_BYTES)   // 129024

__global__ __launch_bounds__(256) void qkv_gemm_kernel(const float* __restrict__ x)
{
    extern __shared__ char smc[];
    const unsigned sbase = smem_u32(smc);
    const int tid  = threadIdx.x;
    const int wid  = tid >> 5;
    const int lane = tid & 31;
    const int wm   = wid & 1;
    const int wn   = wid >> 1;
    const int m0   = blockIdx.x * 64;

    float acc[2][6][4];
#pragma unroll
    for (int f = 0; f < 2; f++)
#pragma unroll
        for (int g = 0; g < 6; g++)
#pragma unroll
            for (int e = 0; e < 4; e++) acc[f][g][e] = 0.f;

    const int a_row = wm * 32 + (lane & 15);
    const int a_col = (lane >> 4) * 8;
    const int b_sub = lane >> 3;
    const int b_row = (b_sub >> 1) * 8 + (lane & 7);
    const int b_col = (b_sub & 1) * 8;

    // --- pipeline prologue: prefetch A(0) into regs, cp.async B(0) ---
    float4 av[4];
#pragma unroll
    for (int it = 0; it < 4; it++) {
        const int i = tid + it * 256;
        const int row = i >> 4, u = i & 15;
        av[it] = *(const float4*)(x + (size_t)(m0 + row) * EMB + u * 4);
    }
#pragma unroll
    for (int i = tid; i < 192 * 8; i += 256) {
        const int row = i >> 3, u = i & 7;
        const unsigned d = sbase + B_OFF + (unsigned)(row * AST + u * 8) * 2;
        CP_ASYNC16(d,               g_Whi + (size_t)row * EMB + u * 8);
        CP_ASYNC16(d + B_HL_BYTES,  g_Wlo + (size_t)row * EMB + u * 8);
    }
    CP_COMMIT();

    for (int c = 0; c < 16; c++) {
        const int c0 = c * 64;
        __syncthreads();   // compute(c-1) done: sA free, B buf[(c+1)&1] free

        // store A(c) regs -> smem (fused fp32->bf16 hi/lo)
#pragma unroll
        for (int it = 0; it < 4; it++) {
            const int i = tid + it * 256;
            const int row = i >> 4, u = i & 15;
            uint2 hp, lp;
            split_hl(av[it].x, av[it].y, hp.x, lp.x);
            split_hl(av[it].z, av[it].w, hp.y, lp.y);
            *(uint2*)(smc + A_HI_OFF + (row * AST + u * 4) * 2) = hp;
            *(uint2*)(smc + A_LO_OFF + (row * AST + u * 4) * 2) = lp;
        }

        float4 av2[4];
        if (c + 1 < 16) {
            const int c1 = c0 + 64;
#pragma unroll
            for (int it = 0; it < 4; it++) {
                const int i = tid + it * 256;
                const int row = i >> 4, u = i & 15;
                av2[it] = *(const float4*)(x + (size_t)(m0 + row) * EMB + c1 + u * 4);
            }
            const unsigned bb = sbase + B_OFF + ((c + 1) & 1) * B_BUF_BYTES;
#pragma unroll
            for (int i = tid; i < 192 * 8; i += 256) {
                const int row = i >> 3, u = i & 7;
                const unsigned d = bb + (unsigned)(row * AST + u * 8) * 2;
                CP_ASYNC16(d,              g_Whi + (size_t)row * EMB + c1 + u * 8);
                CP_ASYNC16(d + B_HL_BYTES, g_Wlo + (size_t)row * EMB + c1 + u * 8);
            }
            CP_COMMIT();
            asm volatile("cp.async.wait_group 1;");
        } else {
            asm volatile("cp.async.wait_group 0;");
        }
        __syncthreads();   // sA stores + B(c) visible

        const unsigned sAhi_u = sbase + A_HI_OFF;
        const unsigned sAlo_u = sbase + A_LO_OFF;
        const unsigned sBhi_u = sbase + B_OFF + (c & 1) * B_BUF_BYTES;
        const unsigned sBlo_u = sBhi_u + B_HL_BYTES;

#pragma unroll
        for (int ks = 0; ks < 4; ks++) {
            unsigned ah[2][4], al[2][4], bh[6][2], bl[6][2];
#pragma unroll
            for (int f = 0; f < 2; f++) {
                const unsigned off = ((a_row + f * 16) * AST + a_col + ks * 16) * 2;
                ldm_x4(sAhi_u + off, ah[f]);
                ldm_x4(sAlo_u + off, al[f]);
            }
#pragma unroll
            for (int p = 0; p < 3; p++) {
                const unsigned off =
                    ((wn * 48 + p * 16 + b_row) * AST + b_col + ks * 16) * 2;
                unsigned t[4];
                ldm_x4(sBhi_u + off, t);
                bh[p * 2][0] = t[0]; bh[p * 2][1] = t[1];
                bh[p * 2 + 1][0] = t[2]; bh[p * 2 + 1][1] = t[3];
                ldm_x4(sBlo_u + off, t);
                bl[p * 2][0] = t[0]; bl[p * 2][1] = t[1];
                bl[p * 2 + 1][0] = t[2]; bl[p * 2 + 1][1] = t[3];
            }
#pragma unroll
            for (int f = 0; f < 2; f++)
#pragma unroll
                for (int g = 0; g < 6; g++) {
                    mma_bf16(acc[f][g], ah[f], bh[g]);
                    mma_bf16(acc[f][g], ah[f], bl[g]);
                    mma_bf16(acc[f][g], al[f], bh[g]);
                }
        }
#pragma unroll
        for (int it = 0; it < 4; it++) av[it] = av2[it];
    }

    // Epilogue: write bf16 hi/lo Q (pre-scaled), K, V
#pragma unroll
    for (int g = 0; g < 6; g++) {
        const int nblk = wn * 48 + g * 8;
        __nv_bfloat16* hb = (nblk < 64) ? g_Qhi : ((nblk < 128) ? g_Khi : g_Vhi);
        __nv_bfloat16* lb = (nblk < 64) ? g_Qlo : ((nblk < 128) ? g_Klo : g_Vlo);
        const float sc = (nblk < 64) ? QSCALE : 1.0f;
        const int coff = (nblk & 63) + (lane & 3) * 2;
#pragma unroll
        for (int f = 0; f < 2; f++) {
            const int row = m0 + wm * 32 + f * 16 + (lane >> 2);
            unsigned h0, l0, h1, l1;
            split_hl(acc[f][g][0] * sc, acc[f][g][1] * sc, h0, l0);
            split_hl(acc[f][g][2] * sc, acc[f][g][3] * sc, h1, l1);
            *(unsigned*)(hb + (size_t)row * HS + coff)       = h0;
            *(unsigned*)(lb + (size_t)row * HS + coff)       = l0;
            *(unsigned*)(hb + (size_t)(row + 8) * HS + coff) = h1;
            *(unsigned*)(lb + (size_t)(row + 8) * HS + coff) = l1;
        }
    }
}

// ---------------------------------------------------------------------------
// Kernel 2: causal flash attention, mma.sync bf16 hi/lo, exp2 domain.
// Variable split-K: qblk 0-7 -> 1 part, 8-15 -> 2, 16-23 -> 3, 24-31 -> 4.
// Every chunk processes <= 8 key tiles. Grid: (80, 4). Heavy-first.
// ---------------------------------------------------------------------------
#define FST 72
#define F_TILE (64 * FST)
#define F_SMEM_BYTES (6 * F_TILE * 2)

__global__ __launch_bounds__(128) void flash_kernel()
{
    extern __shared__ __nv_bfloat16 fs[];
    __nv_bfloat16* sQh = fs;
    __nv_bfloat16* sQl = sQh + F_TILE;
    __nv_bfloat16* sKh = sQl + F_TILE;
    __nv_bfloat16* sKl = sKh + F_TILE;
    __nv_bfloat16* sVh = sKl + F_TILE;
    __nv_bfloat16* sVl = sVh + F_TILE;

    // chunk -> (qblk, part, nsplit), heavy-first
    const int i = blockIdx.x;
    int qblk, part, ns;
    if (i < 32)      { qblk = 31 - (i >> 2);     part = i & 3;        ns = 4; }
    else if (i < 56) { int t = i - 32; qblk = 23 - t / 3; part = t % 3; ns = 3; }
    else if (i < 72) { int t = i - 56; qblk = 15 - (t >> 1); part = t & 1; ns = 2; }
    else             { int t = i - 72; qblk = 7 - t;     part = 0;    ns = 1; }
    const int b  = blockIdx.y;
    const int nt = qblk + 1;
    const int jb = part * nt / ns;
    const int je = (part + 1) * nt / ns;

    const int tid  = threadIdx.x;
    const int w    = tid >> 5;
    const int lane = tid & 31;
    const size_t base = (size_t)b * SEQ * HS;

#pragma unroll
    for (int k = tid; k < 64 * 8; k += 128) {
        const int row = k >> 3, u = k & 7;
        const size_t gi = base + (size_t)(qblk * 64 + row) * HS + u * 8;
        *(uint4*)(sQh + row * FST + u * 8) = *(const uint4*)(g_Qhi + gi);
        *(uint4*)(sQl + row * FST + u * 8) = *(const uint4*)(g_Qlo + gi);
    }
    __syncthreads();

    const unsigned sQh_u = smem_u32(sQh), sQl_u = smem_u32(sQl);
    const unsigned sKh_u = smem_u32(sKh), sKl_u = smem_u32(sKl);
    const unsigned sVh_u = smem_u32(sVh), sVl_u = smem_u32(sVl);
    unsigned qh[4][4], ql[4][4];
    {
        const int ar = w * 16 + (lane & 15);
        const int ac = (lane >> 4) * 8;
#pragma unroll
        for (int ks = 0; ks < 4; ks++) {
            const unsigned off = (ar * FST + ks * 16 + ac) * 2;
            ldm_x4(sQh_u + off, qh[ks]);
            ldm_x4(sQl_u + off, ql[ks]);
        }
    }

    float o[8][4];
#pragma unroll
    for (int nf = 0; nf < 8; nf++)
#pragma unroll
        for (int e = 0; e < 4; e++) o[nf][e] = 0.f;
    float mA = -1e30f, mB = -1e30f, lA = 0.f, lB = 0.f;

    const int b_sub = lane >> 3;
    const int kb_row = (b_sub >> 1) * 8 + (lane & 7);
    const int kb_col = (b_sub & 1) * 8;
    const int vb_row = (b_sub & 1) * 8 + (lane & 7);
    const int vb_col = (b_sub >> 1) * 8;

    for (int j = jb; j < je; j++) {
#pragma unroll
        for (int k = tid; k < 64 * 8; k += 128) {
            const int row = k >> 3, u = k & 7;
            const size_t gi = base + (size_t)(j * 64 + row) * HS + u * 8;
            *(uint4*)(sKh + row * FST + u * 8) = *(const uint4*)(g_Khi + gi);
            *(uint4*)(sKl + row * FST + u * 8) = *(const uint4*)(g_Klo + gi);
            *(uint4*)(sVh + row * FST + u * 8) = *(const uint4*)(g_Vhi + gi);
            *(uint4*)(sVl + row * FST + u * 8) = *(const uint4*)(g_Vlo + gi);
        }
        __syncthreads();

        float s[8][4];
#pragma unroll
        for (int nf = 0; nf < 8; nf++)
#pragma unroll
            for (int e = 0; e < 4; e++) s[nf][e] = 0.f;

#pragma unroll
        for (int ks = 0; ks < 4; ks++) {
            unsigned kh[8][2], kl[8][2];
#pragma unroll
            for (int np = 0; np < 4; np++) {
                const unsigned off = ((np * 16 + kb_row) * FST + ks * 16 + kb_col) * 2;
                unsigned t[4];
                ldm_x4(sKh_u + off, t);
                kh[np * 2][0] = t[0]; kh[np * 2][1] = t[1];
                kh[np * 2 + 1][0] = t[2]; kh[np * 2 + 1][1] = t[3];
                ldm_x4(sKl_u + off, t);
                kl[np * 2][0] = t[0]; kl[np * 2][1] = t[1];
                kl[np * 2 + 1][0] = t[2]; kl[np * 2 + 1][1] = t[3];
            }
#pragma unroll
            for (int nf = 0; nf < 8; nf++) {
                mma_bf16(s[nf], qh[ks], kh[nf]);
                mma_bf16(s[nf], qh[ks], kl[nf]);
                mma_bf16(s[nf], ql[ks], kh[nf]);
            }
        }

        if (j == qblk) {
            const int rA = w * 16 + (lane >> 2);
            const int c0 = (lane & 3) * 2;
#pragma unroll
            for (int nf = 0; nf < 8; nf++) {
                const int c = nf * 8 + c0;
                if (c > rA)         s[nf][0] = -1e30f;
                if (c + 1 > rA)     s[nf][1] = -1e30f;
                if (c > rA + 8)     s[nf][2] = -1e30f;
                if (c + 1 > rA + 8) s[nf][3] = -1e30f;
            }
        }

        float tmA = -1e30f, tmB = -1e30f;
#pragma unroll
        for (int nf = 0; nf < 8; nf++) {
            tmA = fmaxf(tmA, fmaxf(s[nf][0], s[nf][1]));
            tmB = fmaxf(tmB, fmaxf(s[nf][2], s[nf][3]));
        }
#pragma unroll
        for (int off = 1; off < 4; off <<= 1) {
            tmA = fmaxf(tmA, __shfl_xor_sync(0xffffffffu, tmA, off));
            tmB = fmaxf(tmB, __shfl_xor_sync(0xffffffffu, tmB, off));
        }
        const float mnA = fmaxf(mA, tmA), mnB = fmaxf(mB, tmB);
        const float aA = exp2f(mA - mnA), aB = exp2f(mB - mnB);
        mA = mnA; mB = mnB;

        float sumA = 0.f, sumB = 0.f;
#pragma unroll
        for (int nf = 0; nf < 8; nf++) {
            s[nf][0] = exp2f(s[nf][0] - mnA); sumA += s[nf][0];
            s[nf][1] = exp2f(s[nf][1] - mnA); sumA += s[nf][1];
            s[nf][2] = exp2f(s[nf][2] - mnB); sumB += s[nf][2];
            s[nf][3] = exp2f(s[nf][3] - mnB); sumB += s[nf][3];
        }
#pragma unroll
        for (int off = 1; off < 4; off <<= 1) {
            sumA += __shfl_xor_sync(0xffffffffu, sumA, off);
            sumB += __shfl_xor_sync(0xffffffffu, sumB, off);
        }
        lA = lA * aA + sumA;
        lB = lB * aB + sumB;
#pragma unroll
        for (int nf = 0; nf < 8; nf++) {
            o[nf][0] *= aA; o[nf][1] *= aA;
            o[nf][2] *= aB; o[nf][3] *= aB;
        }

#pragma unroll
        for (int ks = 0; ks < 4; ks++) {
            unsigned ah[4], al[4];
            split_hl(s[2 * ks][0],     s[2 * ks][1],     ah[0], al[0]);
            split_hl(s[2 * ks][2],     s[2 * ks][3],     ah[1], al[1]);
            split_hl(s[2 * ks + 1][0], s[2 * ks + 1][1], ah[2], al[2]);
            split_hl(s[2 * ks + 1][2], s[2 * ks + 1][3], ah[3], al[3]);

            unsigned vh[8][2], vl[8][2];
#pragma unroll
            for (int hp = 0; hp < 4; hp++) {
                const unsigned off = ((ks * 16 + vb_row) * FST + hp * 16 + vb_col) * 2;
                unsigned t[4];
                ldm_x4t(sVh_u + off, t);
                vh[hp * 2][0] = t[0]; vh[hp * 2][1] = t[1];
                vh[hp * 2 + 1][0] = t[2]; vh[hp * 2 + 1][1] = t[3];
                ldm_x4t(sVl_u + off, t);
                vl[hp * 2][0] = t[0]; vl[hp * 2][1] = t[1];
                vl[hp * 2 + 1][0] = t[2]; vl[hp * 2 + 1][1] = t[3];
            }
#pragma unroll
            for (int nf = 0; nf < 8; nf++) {
                mma_bf16(o[nf], ah, vh[nf]);
                mma_bf16(o[nf], ah, vl[nf]);
                mma_bf16(o[nf], al, vh[nf]);
            }
        }
        __syncthreads();
    }

    const int rA = qblk * 64 + w * 16 + (lane >> 2);
    const size_t grA = (size_t)b * SEQ + rA;
    const size_t grB = grA + 8;
    const int c0 = (lane & 3) * 2;
#pragma unroll
    for (int nf = 0; nf < 8; nf++) {
        const int c = nf * 8 + c0;
        *(float2*)(&g_Opart[part][grA * HS + c]) = make_float2(o[nf][0], o[nf][1]);
        *(float2*)(&g_Opart[part][grB * HS + c]) = make_float2(o[nf][2], o[nf][3]);
    }
    if ((lane & 3) == 0) {
        g_mpart[part][grA] = mA; g_lpart[part][grA] = lA;
        g_mpart[part][grB] = mB; g_lpart[part][grB] = lB;
    }
}

// ---------------------------------------------------------------------------
// Kernel 3: merge <=4 split-K partials. One thread per output float4.
// ---------------------------------------------------------------------------
__global__ __launch_bounds__(256) void merge_kernel(float* __restrict__ out)
{
    const int idx = blockIdx.x * 256 + threadIdx.x;   // 0 .. MROWS*16-1
    const int r = idx >> 4, u = idx & 15;
    const int t = r & (SEQ - 1);
    const int ns = ((t >> 6) >> 3) + 1;               // 1..4

    float m = -1e30f;
    for (int p = 0; p < ns; p++) m = fmaxf(m, g_mpart[p][r]);
    float a[4], den = 0.f;
    for (int p = 0; p < ns; p++) {
        a[p] = exp2f(g_mpart[p][r] - m);
        den += g_lpart[p][r] * a[p];
    }
    const float inv = 1.f / den;

    float4 acc = make_float4(0.f, 0.f, 0.f, 0.f);
    for (int p = 0; p < ns; p++) {
        float4 v = ((const float4*)(g_Opart[p] + (size_t)r * HS))[u];
        acc.x += v.x * a[p]; acc.y += v.y * a[p];
        acc.z += v.z * a[p]; acc.w += v.w * a[p];
    }
    acc.x *= inv; acc.y *= inv; acc.z *= inv; acc.w *= inv;
    ((float4*)(out + (size_t)r * HS))[u] = acc;
}

// ---------------------------------------------------------------------------

extern "C" void kernel_launch(void* const* d_in, const int* in_sizes, int n_in,
                              void* d_out, int out_size)
{
    const float* x  = (const float*)d_in[0];
    const float* Wq = (const float*)d_in[1];
    const float* Wk = (const float*)d_in[2];
    const float* Wv = (const float*)d_in[3];
    float* out      = (float*)d_out;
    (void)in_sizes; (void)n_in; (void)out_size;

    cudaFuncSetAttribute(qkv_gemm_kernel,
                         cudaFuncAttributeMaxDynamicSharedMemorySize, G_SMEM_BYTES);
    cudaFuncSetAttribute(flash_kernel,
                         cudaFuncAttributeMaxDynamicSharedMemorySize, F_SMEM_BYTES);

    wconv_kernel<<<(NCOMB * EMB / 4 + 255) / 256, 256>>>(Wq, Wk, Wv);
    qkv_gemm_kernel<<<MROWS / 64, 256, G_SMEM_BYTES>>>(x);
    flash_kernel<<<dim3(80, BATCH), 128, F_SMEM_BYTES>>>();
    merge_kernel<<<MROWS * 16 / 256, 256>>>(out);
}